// round 3
// baseline (speedup 1.0000x reference)
#include <cuda_runtime.h>
#include <cuda_bf16.h>
#include <math.h>

// CoxPHLoss without sorting:
//   S[t]  = sum_{j: time_j == t} exp(risk_j)         (4096 buckets)
//   L[t]  = log( sum_{t' >= t} S[t'] )               (suffix logsum)
//   nll   = sum_t d_t * L[t] - sum_{i: event_i} risk_i
// where d_t = number of events in bucket t.
//
// time/event are int32 on the wire (JAX x64 disabled downcasts int64->int32).

#define NBINS 4096
#define GRID1 304
#define THREADS1 1024

// Scratch (device globals; no allocation allowed)
__device__ float  g_partS[GRID1 * NBINS];   // per-block bucket exp-sums
__device__ int    g_partD[GRID1 * NBINS];   // per-block bucket event counts
__device__ double g_partER[GRID1];          // per-block sum of event risks
__device__ double g_S[NBINS];               // reduced bucket sums
__device__ int    g_D[NBINS];               // reduced event counts

// ---------------------------------------------------------------------------
// Kernel 1: streaming histogram pass
// ---------------------------------------------------------------------------
__global__ __launch_bounds__(THREADS1, 2)
void cox_hist_kernel(const float* __restrict__ risk,
                     const int* __restrict__ time_,
                     const int* __restrict__ event_,
                     int n)
{
    __shared__ float s_S[NBINS];
    __shared__ int   s_D[NBINS];
    __shared__ double s_red[32];

    const int tid = threadIdx.x;
    const int bid = blockIdx.x;

    // zero shared histograms
    #pragma unroll
    for (int i = tid; i < NBINS; i += THREADS1) {
        s_S[i] = 0.0f;
        s_D[i] = 0;
    }
    __syncthreads();

    double er = 0.0;  // sum of risk over events (this thread)

    const int nvec = n >> 2;  // 4-element granules
    const float4* r4 = reinterpret_cast<const float4*>(risk);
    const int4*   t4 = reinterpret_cast<const int4*>(time_);
    const int4*   e4 = reinterpret_cast<const int4*>(event_);

    const int gstride = GRID1 * THREADS1;
    const int gtid = bid * THREADS1 + tid;

    for (int i = gtid; i < nvec; i += gstride) {
        float4 r = r4[i];
        int4   t = t4[i];
        int4   e = e4[i];

        int t0 = t.x & (NBINS - 1);
        int t1 = t.y & (NBINS - 1);
        int t2 = t.z & (NBINS - 1);
        int t3 = t.w & (NBINS - 1);

        atomicAdd(&s_S[t0], __expf(r.x));
        atomicAdd(&s_S[t1], __expf(r.y));
        atomicAdd(&s_S[t2], __expf(r.z));
        atomicAdd(&s_S[t3], __expf(r.w));

        if (e.x) { atomicAdd(&s_D[t0], 1); er += (double)r.x; }
        if (e.y) { atomicAdd(&s_D[t1], 1); er += (double)r.y; }
        if (e.z) { atomicAdd(&s_D[t2], 1); er += (double)r.z; }
        if (e.w) { atomicAdd(&s_D[t3], 1); er += (double)r.w; }
    }

    // scalar tail (n not multiple of 4)
    for (int i = (nvec << 2) + gtid; i < n; i += gstride) {
        float r = risk[i];
        int   t = time_[i] & (NBINS - 1);
        atomicAdd(&s_S[t], __expf(r));
        if (event_[i]) { atomicAdd(&s_D[t], 1); er += (double)r; }
    }

    // reduce er within block
    const int lane = tid & 31, wid = tid >> 5;
    #pragma unroll
    for (int off = 16; off > 0; off >>= 1)
        er += __shfl_down_sync(0xffffffffu, er, off);
    if (lane == 0) s_red[wid] = er;
    __syncthreads();
    if (wid == 0) {
        double v = (lane < THREADS1 / 32) ? s_red[lane] : 0.0;
        #pragma unroll
        for (int off = 16; off > 0; off >>= 1)
            v += __shfl_down_sync(0xffffffffu, v, off);
        if (lane == 0) g_partER[bid] = v;
    }
    __syncthreads();

    // flush shared histograms to per-block partials (plain stores, no atomics)
    #pragma unroll
    for (int i = tid; i < NBINS; i += THREADS1) {
        g_partS[bid * NBINS + i] = s_S[i];
        g_partD[bid * NBINS + i] = s_D[i];
    }
}

// ---------------------------------------------------------------------------
// Kernel 2: reduce per-block partials -> g_S (double), g_D
//   One bin per thread; warp reads 32 consecutive bins at the same block
//   index -> coalesced 128B lines.
// ---------------------------------------------------------------------------
__global__ void cox_reduce_kernel()
{
    int bin = blockIdx.x * blockDim.x + threadIdx.x;
    if (bin >= NBINS) return;
    double s = 0.0;
    int d = 0;
    #pragma unroll 4
    for (int g = 0; g < GRID1; g++) {
        s += (double)g_partS[g * NBINS + bin];
        d += g_partD[g * NBINS + bin];
    }
    g_S[bin] = s;
    g_D[bin] = d;
}

// ---------------------------------------------------------------------------
// Kernel 3: suffix scan over 4096 bins + final NLL (single block, 1024 thr)
//   Suffix sum computed as prefix sum of the reversed array.
// ---------------------------------------------------------------------------
__global__ __launch_bounds__(1024, 1)
void cox_final_kernel(float* __restrict__ out)
{
    __shared__ double pref[NBINS];
    __shared__ double warpSums[32];
    __shared__ double redbuf[32];
    __shared__ long long dredbuf[32];

    const int tid = threadIdx.x;
    const int lane = tid & 31, wid = tid >> 5;
    const int base = tid * 4;  // 4 reversed-index elements per thread

    // local inclusive scan of 4 elements (reversed order: a[j] = S[4095-j])
    double v[4];
    double run = 0.0;
    #pragma unroll
    for (int k = 0; k < 4; k++) {
        run += g_S[NBINS - 1 - (base + k)];
        v[k] = run;
    }
    double total = run;

    // warp inclusive scan of per-thread totals
    double x = total;
    #pragma unroll
    for (int off = 1; off < 32; off <<= 1) {
        double y = __shfl_up_sync(0xffffffffu, x, off);
        if (lane >= off) x += y;
    }
    double wexcl = x - total;
    if (lane == 31) warpSums[wid] = x;
    __syncthreads();

    if (wid == 0) {
        double s = warpSums[lane];
        double xx = s;
        #pragma unroll
        for (int off = 1; off < 32; off <<= 1) {
            double y = __shfl_up_sync(0xffffffffu, xx, off);
            if (lane >= off) xx += y;
        }
        warpSums[lane] = xx - s;  // exclusive warp offsets
    }
    __syncthreads();

    double off0 = warpSums[wid] + wexcl;
    #pragma unroll
    for (int k = 0; k < 4; k++)
        pref[base + k] = off0 + v[k];
    __syncthreads();

    // contributions: for bin t with d_t > 0, add d_t * log(suffix_sum[t]).
    // suffix_sum[t] = pref[4095 - t]; this thread owns j = base..base+3.
    double c = 0.0;
    long long dtot = 0;
    #pragma unroll
    for (int k = 0; k < 4; k++) {
        int j = base + k;
        int t = NBINS - 1 - j;
        int d = g_D[t];
        dtot += d;
        if (d > 0) c += (double)d * log(pref[j]);
    }
    // subtract event-risk sum (partials from kernel 1)
    if (tid < GRID1) c -= g_partER[tid];

    // block reduce (c, dtot)
    #pragma unroll
    for (int off = 16; off > 0; off >>= 1) {
        c    += __shfl_down_sync(0xffffffffu, c, off);
        dtot += __shfl_down_sync(0xffffffffu, dtot, off);
    }
    if (lane == 0) { redbuf[wid] = c; dredbuf[wid] = dtot; }
    __syncthreads();
    if (wid == 0) {
        double cc = redbuf[lane];
        long long dd = dredbuf[lane];
        #pragma unroll
        for (int off = 16; off > 0; off >>= 1) {
            cc += __shfl_down_sync(0xffffffffu, cc, off);
            dd += __shfl_down_sync(0xffffffffu, dd, off);
        }
        if (lane == 0)
            out[0] = (dd > 0) ? (float)cc : 0.0f;
    }
}

// ---------------------------------------------------------------------------
extern "C" void kernel_launch(void* const* d_in, const int* in_sizes, int n_in,
                              void* d_out, int out_size)
{
    const float* risk  = (const float*)d_in[0];
    const int*   time_ = (const int*)d_in[1];
    const int*   event_= (const int*)d_in[2];
    float* out = (float*)d_out;
    int n = in_sizes[0];

    cox_hist_kernel<<<GRID1, THREADS1>>>(risk, time_, event_, n);
    cox_reduce_kernel<<<NBINS / 256, 256>>>();
    cox_final_kernel<<<1, 1024>>>(out);
}

// round 5
// speedup vs baseline: 1.5644x; 1.5644x over previous
#include <cuda_runtime.h>
#include <cuda_bf16.h>
#include <math.h>

// CoxPHLoss without sorting:
//   S[t]  = sum_{j: time_j == t} exp(risk_j)         (4096 buckets)
//   L[t]  = log( sum_{t' >= t} S[t'] )               (suffix logsum)
//   nll   = sum_t d_t * L[t] - sum_{i: event_i} risk_i
//
// time/event are int32 on the wire.
// Global bucket sums accumulated in FIXED POINT (2^-20) via integer atomics:
// deterministic combine, no 10MB partial arrays, no separate reduce kernel.

#define NBINS 4096
#define GRID1 304
#define THREADS1 1024
#define FIX_SCALE 1048576.0f   // 2^20
#define FIX_INV   9.5367431640625e-07  // 2^-20 (exact double)

// Scratch (device globals; no allocation allowed)
__device__ unsigned long long g_Sfix[NBINS];  // fixed-point bucket exp-sums
__device__ int                g_D[NBINS];     // bucket event counts
__device__ double             g_partER[GRID1];// per-block sum of event risks

// ---------------------------------------------------------------------------
// Kernel 0: zero the global accumulators (device globals persist across
// graph replays, so this must run every launch).
// ---------------------------------------------------------------------------
__global__ void cox_zero_kernel()
{
    int i = blockIdx.x * blockDim.x + threadIdx.x;
    if (i < NBINS) {
        g_Sfix[i] = 0ull;
        g_D[i] = 0;
    }
}

// ---------------------------------------------------------------------------
// Kernel 1: streaming histogram pass (shared-mem atomics), then flush the
// per-block histogram into the global fixed-point accumulators.
// ---------------------------------------------------------------------------
__global__ __launch_bounds__(THREADS1, 2)
void cox_hist_kernel(const float* __restrict__ risk,
                     const int* __restrict__ time_,
                     const int* __restrict__ event_,
                     int n)
{
    __shared__ float s_S[NBINS];
    __shared__ int   s_D[NBINS];
    __shared__ double s_red[32];

    const int tid = threadIdx.x;
    const int bid = blockIdx.x;

    #pragma unroll
    for (int i = tid; i < NBINS; i += THREADS1) {
        s_S[i] = 0.0f;
        s_D[i] = 0;
    }
    __syncthreads();

    double er = 0.0;  // sum of risk over events (this thread)

    const int nvec = n >> 2;
    const float4* r4 = reinterpret_cast<const float4*>(risk);
    const int4*   t4 = reinterpret_cast<const int4*>(time_);
    const int4*   e4 = reinterpret_cast<const int4*>(event_);

    const int gstride = GRID1 * THREADS1;
    const int gtid = bid * THREADS1 + tid;

    for (int i = gtid; i < nvec; i += gstride) {
        float4 r = r4[i];
        int4   t = t4[i];
        int4   e = e4[i];

        int t0 = t.x & (NBINS - 1);
        int t1 = t.y & (NBINS - 1);
        int t2 = t.z & (NBINS - 1);
        int t3 = t.w & (NBINS - 1);

        atomicAdd(&s_S[t0], __expf(r.x));
        atomicAdd(&s_S[t1], __expf(r.y));
        atomicAdd(&s_S[t2], __expf(r.z));
        atomicAdd(&s_S[t3], __expf(r.w));

        if (e.x) { atomicAdd(&s_D[t0], 1); er += (double)r.x; }
        if (e.y) { atomicAdd(&s_D[t1], 1); er += (double)r.y; }
        if (e.z) { atomicAdd(&s_D[t2], 1); er += (double)r.z; }
        if (e.w) { atomicAdd(&s_D[t3], 1); er += (double)r.w; }
    }

    // scalar tail
    for (int i = (nvec << 2) + gtid; i < n; i += gstride) {
        float r = risk[i];
        int   t = time_[i] & (NBINS - 1);
        atomicAdd(&s_S[t], __expf(r));
        if (event_[i]) { atomicAdd(&s_D[t], 1); er += (double)r; }
    }

    // reduce er within block -> g_partER[bid]
    const int lane = tid & 31, wid = tid >> 5;
    #pragma unroll
    for (int off = 16; off > 0; off >>= 1)
        er += __shfl_down_sync(0xffffffffu, er, off);
    if (lane == 0) s_red[wid] = er;
    __syncthreads();
    if (wid == 0) {
        double v = s_red[lane];
        #pragma unroll
        for (int off = 16; off > 0; off >>= 1)
            v += __shfl_down_sync(0xffffffffu, v, off);
        if (lane == 0) g_partER[bid] = v;
    }
    __syncthreads();

    // flush shared histogram -> global fixed-point accumulators.
    // Integer atomics => deterministic global combine.
    #pragma unroll
    for (int i = tid; i < NBINS; i += THREADS1) {
        float s = s_S[i];
        int   d = s_D[i];
        if (s != 0.0f) {
            unsigned long long fx =
                __float2ull_rn(s * FIX_SCALE);
            atomicAdd(&g_Sfix[i], fx);
        }
        if (d != 0) atomicAdd(&g_D[i], d);
    }
}

// ---------------------------------------------------------------------------
// Kernel 2: suffix scan over 4096 bins + final NLL (single block, 1024 thr)
// ---------------------------------------------------------------------------
__global__ __launch_bounds__(1024, 1)
void cox_final_kernel(float* __restrict__ out)
{
    __shared__ double pref[NBINS];
    __shared__ double warpSums[32];
    __shared__ double redbuf[32];
    __shared__ long long dredbuf[32];

    const int tid = threadIdx.x;
    const int lane = tid & 31, wid = tid >> 5;
    const int base = tid * 4;  // 4 reversed-index elements per thread

    // local inclusive scan of 4 elements (reversed order: a[j] = S[4095-j])
    double v[4];
    double run = 0.0;
    #pragma unroll
    for (int k = 0; k < 4; k++) {
        unsigned long long fx = g_Sfix[NBINS - 1 - (base + k)];
        run += (double)fx * FIX_INV;
        v[k] = run;
    }
    double total = run;

    // warp inclusive scan of per-thread totals
    double x = total;
    #pragma unroll
    for (int off = 1; off < 32; off <<= 1) {
        double y = __shfl_up_sync(0xffffffffu, x, off);
        if (lane >= off) x += y;
    }
    double wexcl = x - total;
    if (lane == 31) warpSums[wid] = x;
    __syncthreads();

    if (wid == 0) {
        double s = warpSums[lane];
        double xx = s;
        #pragma unroll
        for (int off = 1; off < 32; off <<= 1) {
            double y = __shfl_up_sync(0xffffffffu, xx, off);
            if (lane >= off) xx += y;
        }
        warpSums[lane] = xx - s;  // exclusive warp offsets
    }
    __syncthreads();

    double off0 = warpSums[wid] + wexcl;
    #pragma unroll
    for (int k = 0; k < 4; k++)
        pref[base + k] = off0 + v[k];
    __syncthreads();

    // for bin t with d_t > 0: add d_t * log(suffix_sum[t]);
    // suffix_sum[t] = pref[4095 - t]
    double c = 0.0;
    long long dtot = 0;
    #pragma unroll
    for (int k = 0; k < 4; k++) {
        int j = base + k;
        int t = NBINS - 1 - j;
        int d = g_D[t];
        dtot += d;
        if (d > 0) c += (double)d * log(pref[j]);
    }
    // subtract event-risk sum
    if (tid < GRID1) c -= g_partER[tid];

    // block reduce (c, dtot)
    #pragma unroll
    for (int off = 16; off > 0; off >>= 1) {
        c    += __shfl_down_sync(0xffffffffu, c, off);
        dtot += __shfl_down_sync(0xffffffffu, dtot, off);
    }
    if (lane == 0) { redbuf[wid] = c; dredbuf[wid] = dtot; }
    __syncthreads();
    if (wid == 0) {
        double cc = redbuf[lane];
        long long dd = dredbuf[lane];
        #pragma unroll
        for (int off = 16; off > 0; off >>= 1) {
            cc += __shfl_down_sync(0xffffffffu, cc, off);
            dd += __shfl_down_sync(0xffffffffu, dd, off);
        }
        if (lane == 0)
            out[0] = (dd > 0) ? (float)cc : 0.0f;
    }
}

// ---------------------------------------------------------------------------
extern "C" void kernel_launch(void* const* d_in, const int* in_sizes, int n_in,
                              void* d_out, int out_size)
{
    const float* risk  = (const float*)d_in[0];
    const int*   time_ = (const int*)d_in[1];
    const int*   event_= (const int*)d_in[2];
    float* out = (float*)d_out;
    int n = in_sizes[0];

    cox_zero_kernel<<<(NBINS + 511) / 512, 512>>>();
    cox_hist_kernel<<<GRID1, THREADS1>>>(risk, time_, event_, n);
    cox_final_kernel<<<1, 1024>>>(out);
}